// round 7
// baseline (speedup 1.0000x reference)
#include <cuda_runtime.h>
#include <cuda_bf16.h>

// SE3Transform (PARTIAL_DENSE): for m in [0,M), i in [0,N):
//   nb = batch[i] + m*B;  out_pos[m*N+i] = R[nb] @ xyz[i] + p[nb];  out_batch[m*N+i] = nb
// Inputs: trans [M*B,4,4] f32, xyz [N,3] f32, batch [N] i32.
// Output: new_pos.ravel() [M*N*3] f32 ++ new_batch [M*N] as f32.
//
// R5 findings: latency-bound (L1 51%, issue 21%, occupancy bump was neutral).
// R6/R7: 2 independent 4-point groups per thread (MLP=8 front loads, dual
// compute chains), groups blockDim-strided to keep the 48B lane stride (no
// extra line inflation). 978 CTAs @128thr -> whole grid resident in one wave.

#define BATCH_B 16
#define NMAT    128          // M*B
#define NPAIR   6            // float2 pairs per matrix (12 floats)
#define SL      4            // slices handled per thread

struct Grp {
    float x[4], y[4], z[4];
    int   b0[4];
    float fb0[4];
};

__device__ __forceinline__ void load_grp(Grp& G_, const float4* __restrict__ xyz4,
                                         const int4* __restrict__ batch4, int g)
{
    float4 a = __ldg(&xyz4[g * 3 + 0]);
    float4 b = __ldg(&xyz4[g * 3 + 1]);
    float4 c = __ldg(&xyz4[g * 3 + 2]);
    int4  bt = __ldg(&batch4[g]);
    G_.x[0] = a.x; G_.y[0] = a.y; G_.z[0] = a.z;
    G_.x[1] = a.w; G_.y[1] = b.x; G_.z[1] = b.y;
    G_.x[2] = b.z; G_.y[2] = b.w; G_.z[2] = c.x;
    G_.x[3] = c.y; G_.y[3] = c.z; G_.z[3] = c.w;
    G_.b0[0] = bt.x; G_.b0[1] = bt.y; G_.b0[2] = bt.z; G_.b0[3] = bt.w;
    G_.fb0[0] = (float)bt.x; G_.fb0[1] = (float)bt.y;
    G_.fb0[2] = (float)bt.z; G_.fb0[3] = (float)bt.w;
}

__device__ __forceinline__ void do_slice(const Grp& G_, const float2* __restrict__ s2,
                                         float* __restrict__ out, int i0,
                                         int mB, float fmB, long long sliceBase,
                                         long long posElems, int writeBatch)
{
    float o[12];
    #pragma unroll
    for (int k = 0; k < 4; k++) {
        int nb = G_.b0[k] + mB;
        float2 p0 = s2[0 * NMAT + nb];  // r00 r01
        float2 p1 = s2[1 * NMAT + nb];  // r02 tx
        float2 p2 = s2[2 * NMAT + nb];  // r10 r11
        float2 p3 = s2[3 * NMAT + nb];  // r12 ty
        float2 p4 = s2[4 * NMAT + nb];  // r20 r21
        float2 p5 = s2[5 * NMAT + nb];  // r22 tz
        o[k*3+0] = fmaf(p0.x, G_.x[k], fmaf(p0.y, G_.y[k], fmaf(p1.x, G_.z[k], p1.y)));
        o[k*3+1] = fmaf(p2.x, G_.x[k], fmaf(p2.y, G_.y[k], fmaf(p3.x, G_.z[k], p3.y)));
        o[k*3+2] = fmaf(p4.x, G_.x[k], fmaf(p4.y, G_.y[k], fmaf(p5.x, G_.z[k], p5.y)));
    }

    float4* outv = (float4*)(out + (sliceBase + i0) * 3);
    outv[0] = make_float4(o[0], o[1], o[2],  o[3]);
    outv[1] = make_float4(o[4], o[5], o[6],  o[7]);
    outv[2] = make_float4(o[8], o[9], o[10], o[11]);

    if (writeBatch) {
        float4* bo = (float4*)(out + posElems + sliceBase + i0);
        *bo = make_float4(G_.fb0[0] + fmB, G_.fb0[1] + fmB,
                          G_.fb0[2] + fmB, G_.fb0[3] + fmB);
    }
}

__device__ __forceinline__ void scalar_tail(const float* __restrict__ xyz,
                                            const int* __restrict__ batch,
                                            const float2* __restrict__ s2,
                                            float* __restrict__ out,
                                            int i0, int N, int m0, int M,
                                            long long posElems, int writeBatch)
{
    for (int i = i0; i < N; i++) {
        float px = xyz[i * 3 + 0];
        float py = xyz[i * 3 + 1];
        float pz = xyz[i * 3 + 2];
        int bi = __ldg(&batch[i]);
        for (int s = 0; s < SL; s++) {
            int m = m0 + s;
            if (m >= M) break;
            int nb = bi + m * BATCH_B;
            float2 p0 = s2[0 * NMAT + nb];
            float2 p1 = s2[1 * NMAT + nb];
            float2 p2 = s2[2 * NMAT + nb];
            float2 p3 = s2[3 * NMAT + nb];
            float2 p4 = s2[4 * NMAT + nb];
            float2 p5 = s2[5 * NMAT + nb];
            long long ob = ((long long)m * N + i) * 3;
            out[ob + 0] = fmaf(p0.x, px, fmaf(p0.y, py, fmaf(p1.x, pz, p1.y)));
            out[ob + 1] = fmaf(p2.x, px, fmaf(p2.y, py, fmaf(p3.x, pz, p3.y)));
            out[ob + 2] = fmaf(p4.x, px, fmaf(p4.y, py, fmaf(p5.x, pz, p5.y)));
            if (writeBatch)
                out[posElems + (long long)m * N + i] = (float)nb;
        }
    }
}

__global__ void __launch_bounds__(128, 8) se3_kernel(
        const float*  __restrict__ trans,
        const float4* __restrict__ xyz4,
        const float*  __restrict__ xyz,
        const int4*   __restrict__ batch4,
        const int*    __restrict__ batch,
        float* __restrict__ out,
        int N, int G, int M,
        long long posElems, int writeBatch)
{
    __shared__ float2 s2[NPAIR * NMAT];   // 6 KB float2-SoA table (conflict-free)

    for (int idx = threadIdx.x; idx < NPAIR * NMAT; idx += blockDim.x) {
        int j   = idx >> 7;
        int mat = idx & 127;
        const float2* src = (const float2*)(trans + mat * 16);
        s2[idx] = __ldg(&src[j]);
    }
    __syncthreads();

    const int m0 = blockIdx.y * SL;
    const int baseG = blockIdx.x * (blockDim.x * 2);
    const int ga = baseG + threadIdx.x;
    const int gb = baseG + blockDim.x + threadIdx.x;

    const int iA = ga * 4;
    const int iB = gb * 4;
    const bool fA = (ga < G) && (iA + 3 < N);
    const bool fB = (gb < G) && (iB + 3 < N);

    Grp A, B;
    if (fA) load_grp(A, xyz4, batch4, ga);   // 4 LDG, independent
    if (fB) load_grp(B, xyz4, batch4, gb);   // 4 more LDG -> MLP 8

    if (fA && fB) {
        #pragma unroll
        for (int s = 0; s < SL; s++) {
            int m = m0 + s;
            if (m >= M) break;
            int mB = m * BATCH_B;
            float fmB = (float)mB;
            long long sliceBase = (long long)m * N;
            do_slice(A, s2, out, iA, mB, fmB, sliceBase, posElems, writeBatch);
            do_slice(B, s2, out, iB, mB, fmB, sliceBase, posElems, writeBatch);
        }
        return;
    }

    // rare edges: handle each group independently
    if (fA) {
        #pragma unroll
        for (int s = 0; s < SL; s++) {
            int m = m0 + s;
            if (m >= M) break;
            do_slice(A, s2, out, iA, m * BATCH_B, (float)(m * BATCH_B),
                     (long long)m * N, posElems, writeBatch);
        }
    } else if (ga < G) {
        scalar_tail(xyz, batch, s2, out, iA, N, m0, M, posElems, writeBatch);
    }
    if (fB) {
        #pragma unroll
        for (int s = 0; s < SL; s++) {
            int m = m0 + s;
            if (m >= M) break;
            do_slice(B, s2, out, iB, m * BATCH_B, (float)(m * BATCH_B),
                     (long long)m * N, posElems, writeBatch);
        }
    } else if (gb < G) {
        scalar_tail(xyz, batch, s2, out, iB, N, m0, M, posElems, writeBatch);
    }
}

extern "C" void kernel_launch(void* const* d_in, const int* in_sizes, int n_in,
                              void* d_out, int out_size) {
    const float* trans = (const float*)d_in[0];   // [M*B, 4, 4]
    const float* xyz   = (const float*)d_in[1];   // [N, 3]
    const int*   batch = (const int*)d_in[2];     // [N]

    int numMat = in_sizes[0] / 16;        // M*B (= 128)
    int M      = numMat / BATCH_B;        // 8
    int N      = in_sizes[2];             // 500000

    long long posElems = (long long)M * N * 3;
    int writeBatch = ((long long)out_size >= posElems + (long long)M * N) ? 1 : 0;

    int G = (N + 3) / 4;                  // 4-point groups (125000)
    int threads = 128;
    int perBlock = threads * 2;           // 2 groups per thread
    int blocksX = (G + perBlock - 1) / perBlock;   // 489
    int blocksY = (M + SL - 1) / SL;               // 2

    dim3 grid(blocksX, blocksY, 1);
    se3_kernel<<<grid, threads>>>(
        trans,
        (const float4*)xyz, xyz,
        (const int4*)batch, batch,
        (float*)d_out,
        N, G, M, posElems, writeBatch);
}

// round 8
// speedup vs baseline: 1.0268x; 1.0268x over previous
#include <cuda_runtime.h>
#include <cuda_bf16.h>

// SE3Transform (PARTIAL_DENSE): for m in [0,M), i in [0,N):
//   nb = batch[i] + m*B;  out_pos[m*N+i] = R[nb] @ xyz[i] + p[nb];  out_batch[m*N+i] = nb
// Inputs: trans [M*B,4,4] f32, xyz [N,3] f32, batch [N] i32.
// Output: new_pos.ravel() [M*N*3] f32 ++ new_batch [M*N] as f32.
//
// R7 findings: dur invariant (~23us) across occ/ILP variants; nothing
// saturated -> exposed-latency bound, fix is per-thread work amortization.
// R8: SL=8 (all slices per thread), blocksY=1. Inputs read once per point,
// ~1200cyc of dependent work behind each ~250-600cyc front load. 977 CTAs
// @128thr, <=8 CTA/SM -> single wave, ~6% tail imbalance.

#define BATCH_B 16
#define NMAT    128          // M*B
#define NPAIR   6            // float2 pairs per matrix (12 floats)

__global__ void __launch_bounds__(128, 8) se3_kernel(
        const float*  __restrict__ trans,
        const float4* __restrict__ xyz4,
        const float*  __restrict__ xyz,
        const int4*   __restrict__ batch4,
        const int*    __restrict__ batch,
        float* __restrict__ out,
        int N, int G, int M,
        long long posElems, int writeBatch)
{
    // float2-SoA transform table: s2[j*NMAT + mat] = (trans[mat][2j], trans[mat][2j+1])
    __shared__ float2 s2[NPAIR * NMAT];   // 6 KB, conflict-free gathers

    for (int idx = threadIdx.x; idx < NPAIR * NMAT; idx += blockDim.x) {
        int j   = idx >> 7;
        int mat = idx & 127;
        const float2* src = (const float2*)(trans + mat * 16);
        s2[idx] = __ldg(&src[j]);
    }
    __syncthreads();

    for (int g = blockIdx.x * blockDim.x + threadIdx.x; g < G;
         g += gridDim.x * blockDim.x)
    {
        const int i0 = g * 4;

        if (i0 + 3 < N) {
            // ---- load 4 points once (these are the only input reads) ----
            float4 a = __ldg(&xyz4[g * 3 + 0]);
            float4 b = __ldg(&xyz4[g * 3 + 1]);
            float4 c = __ldg(&xyz4[g * 3 + 2]);
            int4  bt = __ldg(&batch4[g]);

            float x[4], y[4], z[4];
            x[0] = a.x; y[0] = a.y; z[0] = a.z;
            x[1] = a.w; y[1] = b.x; z[1] = b.y;
            x[2] = b.z; y[2] = b.w; z[2] = c.x;
            x[3] = c.y; y[3] = c.z; z[3] = c.w;

            int b0[4];
            b0[0] = bt.x; b0[1] = bt.y; b0[2] = bt.z; b0[3] = bt.w;
            float fb0[4];
            fb0[0] = (float)bt.x; fb0[1] = (float)bt.y;
            fb0[2] = (float)bt.z; fb0[3] = (float)bt.w;

            // ---- all M slices from this thread ----
            for (int m = 0; m < M; m++) {
                int mB = m * BATCH_B;
                float fmB = (float)mB;
                long long sliceBase = (long long)m * N;

                float o[12];
                #pragma unroll
                for (int k = 0; k < 4; k++) {
                    int nb = b0[k] + mB;
                    float2 p0 = s2[0 * NMAT + nb];  // r00 r01
                    float2 p1 = s2[1 * NMAT + nb];  // r02 tx
                    float2 p2 = s2[2 * NMAT + nb];  // r10 r11
                    float2 p3 = s2[3 * NMAT + nb];  // r12 ty
                    float2 p4 = s2[4 * NMAT + nb];  // r20 r21
                    float2 p5 = s2[5 * NMAT + nb];  // r22 tz
                    o[k*3+0] = fmaf(p0.x, x[k], fmaf(p0.y, y[k], fmaf(p1.x, z[k], p1.y)));
                    o[k*3+1] = fmaf(p2.x, x[k], fmaf(p2.y, y[k], fmaf(p3.x, z[k], p3.y)));
                    o[k*3+2] = fmaf(p4.x, x[k], fmaf(p4.y, y[k], fmaf(p5.x, z[k], p5.y)));
                }

                float4* outv = (float4*)(out + (sliceBase + i0) * 3);
                outv[0] = make_float4(o[0], o[1], o[2],  o[3]);
                outv[1] = make_float4(o[4], o[5], o[6],  o[7]);
                outv[2] = make_float4(o[8], o[9], o[10], o[11]);

                if (writeBatch) {
                    float4* bo = (float4*)(out + posElems + sliceBase + i0);
                    *bo = make_float4(fb0[0] + fmB, fb0[1] + fmB,
                                      fb0[2] + fmB, fb0[3] + fmB);
                }
            }
        } else {
            // ---- scalar tail ----
            for (int i = i0; i < N; i++) {
                float px = xyz[i * 3 + 0];
                float py = xyz[i * 3 + 1];
                float pz = xyz[i * 3 + 2];
                int bi = __ldg(&batch[i]);
                for (int m = 0; m < M; m++) {
                    int nb = bi + m * BATCH_B;
                    float2 p0 = s2[0 * NMAT + nb];
                    float2 p1 = s2[1 * NMAT + nb];
                    float2 p2 = s2[2 * NMAT + nb];
                    float2 p3 = s2[3 * NMAT + nb];
                    float2 p4 = s2[4 * NMAT + nb];
                    float2 p5 = s2[5 * NMAT + nb];
                    long long ob = ((long long)m * N + i) * 3;
                    out[ob + 0] = fmaf(p0.x, px, fmaf(p0.y, py, fmaf(p1.x, pz, p1.y)));
                    out[ob + 1] = fmaf(p2.x, px, fmaf(p2.y, py, fmaf(p3.x, pz, p3.y)));
                    out[ob + 2] = fmaf(p4.x, px, fmaf(p4.y, py, fmaf(p5.x, pz, p5.y)));
                    if (writeBatch)
                        out[posElems + (long long)m * N + i] = (float)nb;
                }
            }
        }
    }
}

extern "C" void kernel_launch(void* const* d_in, const int* in_sizes, int n_in,
                              void* d_out, int out_size) {
    const float* trans = (const float*)d_in[0];   // [M*B, 4, 4]
    const float* xyz   = (const float*)d_in[1];   // [N, 3]
    const int*   batch = (const int*)d_in[2];     // [N]

    int numMat = in_sizes[0] / 16;        // M*B (= 128)
    int M      = numMat / BATCH_B;        // 8
    int N      = in_sizes[2];             // 500000

    long long posElems = (long long)M * N * 3;
    int writeBatch = ((long long)out_size >= posElems + (long long)M * N) ? 1 : 0;

    int G = (N + 3) / 4;                  // 4-point groups (125000)
    int threads = 128;
    int blocksX = (G + threads - 1) / threads;   // 977
    if (blocksX > 65535) blocksX = 65535;

    se3_kernel<<<blocksX, threads>>>(
        trans,
        (const float4*)xyz, xyz,
        (const int4*)batch, batch,
        (float*)d_out,
        N, G, M, posElems, writeBatch);
}

// round 10
// speedup vs baseline: 1.0931x; 1.0646x over previous
#include <cuda_runtime.h>
#include <cuda_bf16.h>

// SE3Transform (PARTIAL_DENSE): for m in [0,M), i in [0,N):
//   nb = batch[i] + m*B;  out_pos[m*N+i] = R[nb] @ xyz[i] + p[nb];  out_batch[m*N+i] = nb
// Inputs: trans [M*B,4,4] f32, xyz [N,3] f32, batch [N] i32.
// Output: new_pos.ravel() [M*N*3] f32 ++ new_batch [M*N] as f32.
//
// R8 findings: dur ~22.7us invariant across occ/ILP/slices-per-thread; no pipe
// >53%. Diagnosis: multi-CTA spread (cross-CTA L1tex queue contention at
// oe~7, MLP_p1~4-8) -> slowest-CTA bound at ~50% port util.
// R9/R10 (mode-W): one fat CTA per SM — grid = 152, block = 832 (26 warps),
// balanced contiguous group ranges. Inner body identical to R8.

#define BATCH_B 16
#define NMAT    128          // M*B
#define NPAIR   6            // float2 pairs per matrix (12 floats)
#define NSM     152          // GB300 SM count

__global__ void __launch_bounds__(832, 1) se3_kernel(
        const float*  __restrict__ trans,
        const float4* __restrict__ xyz4,
        const float*  __restrict__ xyz,
        const int4*   __restrict__ batch4,
        const int*    __restrict__ batch,
        float* __restrict__ out,
        int N, int G, int M,
        long long posElems, int writeBatch)
{
    // float2-SoA transform table: s2[j*NMAT + mat] = (trans[mat][2j], trans[mat][2j+1])
    __shared__ float2 s2[NPAIR * NMAT];   // 6 KB, conflict-free gathers

    for (int idx = threadIdx.x; idx < NPAIR * NMAT; idx += blockDim.x) {
        int j   = idx >> 7;
        int mat = idx & 127;
        const float2* src = (const float2*)(trans + mat * 16);
        s2[idx] = __ldg(&src[j]);
    }
    __syncthreads();

    // Balanced contiguous group range for this CTA (one CTA per SM).
    const int gStart = (int)((long long)blockIdx.x * G / gridDim.x);
    const int gEnd   = (int)((long long)(blockIdx.x + 1) * G / gridDim.x);
    const int g = gStart + threadIdx.x;
    if (g >= gEnd) return;

    const int i0 = g * 4;

    if (i0 + 3 < N) {
        // ---- load 4 points once (the only input reads) ----
        float4 a = __ldg(&xyz4[g * 3 + 0]);
        float4 b = __ldg(&xyz4[g * 3 + 1]);
        float4 c = __ldg(&xyz4[g * 3 + 2]);
        int4  bt = __ldg(&batch4[g]);

        float x[4], y[4], z[4];
        x[0] = a.x; y[0] = a.y; z[0] = a.z;
        x[1] = a.w; y[1] = b.x; z[1] = b.y;
        x[2] = b.z; y[2] = b.w; z[2] = c.x;
        x[3] = c.y; y[3] = c.z; z[3] = c.w;

        int b0[4];
        b0[0] = bt.x; b0[1] = bt.y; b0[2] = bt.z; b0[3] = bt.w;
        float fb0[4];
        fb0[0] = (float)bt.x; fb0[1] = (float)bt.y;
        fb0[2] = (float)bt.z; fb0[3] = (float)bt.w;

        // ---- all M slices from this thread ----
        for (int m = 0; m < M; m++) {
            int mB = m * BATCH_B;
            float fmB = (float)mB;
            long long sliceBase = (long long)m * N;

            float o[12];
            #pragma unroll
            for (int k = 0; k < 4; k++) {
                int nb = b0[k] + mB;
                float2 p0 = s2[0 * NMAT + nb];  // r00 r01
                float2 p1 = s2[1 * NMAT + nb];  // r02 tx
                float2 p2 = s2[2 * NMAT + nb];  // r10 r11
                float2 p3 = s2[3 * NMAT + nb];  // r12 ty
                float2 p4 = s2[4 * NMAT + nb];  // r20 r21
                float2 p5 = s2[5 * NMAT + nb];  // r22 tz
                o[k*3+0] = fmaf(p0.x, x[k], fmaf(p0.y, y[k], fmaf(p1.x, z[k], p1.y)));
                o[k*3+1] = fmaf(p2.x, x[k], fmaf(p2.y, y[k], fmaf(p3.x, z[k], p3.y)));
                o[k*3+2] = fmaf(p4.x, x[k], fmaf(p4.y, y[k], fmaf(p5.x, z[k], p5.y)));
            }

            float4* outv = (float4*)(out + (sliceBase + i0) * 3);
            outv[0] = make_float4(o[0], o[1], o[2],  o[3]);
            outv[1] = make_float4(o[4], o[5], o[6],  o[7]);
            outv[2] = make_float4(o[8], o[9], o[10], o[11]);

            if (writeBatch) {
                float4* bo = (float4*)(out + posElems + sliceBase + i0);
                *bo = make_float4(fb0[0] + fmB, fb0[1] + fmB,
                                  fb0[2] + fmB, fb0[3] + fmB);
            }
        }
    } else {
        // ---- scalar tail (unused when N % 4 == 0, kept for safety) ----
        for (int i = i0; i < N; i++) {
            float px = xyz[i * 3 + 0];
            float py = xyz[i * 3 + 1];
            float pz = xyz[i * 3 + 2];
            int bi = __ldg(&batch[i]);
            for (int m = 0; m < M; m++) {
                int nb = bi + m * BATCH_B;
                float2 p0 = s2[0 * NMAT + nb];
                float2 p1 = s2[1 * NMAT + nb];
                float2 p2 = s2[2 * NMAT + nb];
                float2 p3 = s2[3 * NMAT + nb];
                float2 p4 = s2[4 * NMAT + nb];
                float2 p5 = s2[5 * NMAT + nb];
                long long ob = ((long long)m * N + i) * 3;
                out[ob + 0] = fmaf(p0.x, px, fmaf(p0.y, py, fmaf(p1.x, pz, p1.y)));
                out[ob + 1] = fmaf(p2.x, px, fmaf(p2.y, py, fmaf(p3.x, pz, p3.y)));
                out[ob + 2] = fmaf(p4.x, px, fmaf(p4.y, py, fmaf(p5.x, pz, p5.y)));
                if (writeBatch)
                    out[posElems + (long long)m * N + i] = (float)nb;
            }
        }
    }
}

extern "C" void kernel_launch(void* const* d_in, const int* in_sizes, int n_in,
                              void* d_out, int out_size) {
    const float* trans = (const float*)d_in[0];   // [M*B, 4, 4]
    const float* xyz   = (const float*)d_in[1];   // [N, 3]
    const int*   batch = (const int*)d_in[2];     // [N]

    int numMat = in_sizes[0] / 16;        // M*B (= 128)
    int M      = numMat / BATCH_B;        // 8
    int N      = in_sizes[2];             // 500000

    long long posElems = (long long)M * N * 3;
    int writeBatch = ((long long)out_size >= posElems + (long long)M * N) ? 1 : 0;

    int G = (N + 3) / 4;                  // 4-point groups (125000)

    // One fat CTA per SM (mode-W): grid = 152 (GB300), 832 threads = 26 warps.
    int blocks = NSM;
    int threads = 832;
    // Safety: ensure every group is covered (perCTA <= threads).
    int perCTA = (G + blocks - 1) / blocks;
    if (perCTA > threads) {
        blocks = (G + threads - 1) / threads;
    }

    se3_kernel<<<blocks, threads>>>(
        trans,
        (const float4*)xyz, xyz,
        (const int4*)batch, batch,
        (float*)d_out,
        N, G, M, posElems, writeBatch);
}